// round 1
// baseline (speedup 1.0000x reference)
#include <cuda_runtime.h>

#define BB   16
#define SEQ  512
#define NH   8
#define DH   128
#define HD   1024                 // NH*DH
#define NROWS (BB*SEQ)            // 8192
#define SCALE 0.08838834764831843f

// Scratch (no device allocation allowed)
__device__ float g_q [BB*NH*SEQ*DH];   // [B,H,N,D]  masked*scaled
__device__ float g_k [BB*NH*SEQ*DH];   // [B,H,N,D]  masked
__device__ float g_v [BB*NH*SEQ*DH];   // [B,H,N,D]  masked
__device__ float g_y1[NROWS*HD];       // [B,N,H*D]  attention output

// ---------------------------------------------------------------------------
// QKV projection: out = (x @ W + b) * mask (* scale for q), scattered to [B,H,N,D]
// grid: (HD/64, NROWS/64, 3)   block: 256  (16x16 threads, 4x4 micro-tile)
// ---------------------------------------------------------------------------
__global__ __launch_bounds__(256) void proj_kernel(
    const float* __restrict__ x,  const float* __restrict__ mask,
    const float* __restrict__ Wq, const float* __restrict__ bq,
    const float* __restrict__ Wk, const float* __restrict__ bk,
    const float* __restrict__ Wv, const float* __restrict__ bv)
{
    __shared__ float XsT[64*64];   // [kk][r]
    __shared__ float Ws [64*64];   // [kk][c]
    const int tid = threadIdx.x;
    const int tx = tid & 15, ty = tid >> 4;
    const int c0 = blockIdx.x * 64;
    const int r0 = blockIdx.y * 64;
    const int sel = blockIdx.z;
    const float* W    = (sel == 0) ? Wq : (sel == 1) ? Wk : Wv;
    const float* bias = (sel == 0) ? bq : (sel == 1) ? bk : bv;
    float*       out  = (sel == 0) ? g_q : (sel == 1) ? g_k : g_v;
    const float extra = (sel == 0) ? SCALE : 1.0f;

    float acc[4][4];
#pragma unroll
    for (int r = 0; r < 4; r++)
#pragma unroll
        for (int c = 0; c < 4; c++) acc[r][c] = 0.0f;

    for (int kc = 0; kc < 2; kc++) {
        __syncthreads();
        const int k0 = kc * 64;
        for (int i = tid; i < 4096; i += 256) {
            int r = i >> 6, kk = i & 63;
            XsT[kk*64 + r] = x[(size_t)(r0 + r) * DH + k0 + kk];
        }
        for (int i = tid; i < 4096; i += 256) {
            int kk = i >> 6, c = i & 63;
            Ws[i] = W[(size_t)(k0 + kk) * HD + c0 + c];
        }
        __syncthreads();
#pragma unroll 8
        for (int kk = 0; kk < 64; kk++) {
            float4 a = *(const float4*)&XsT[kk*64 + ty*4];
            float4 b = *(const float4*)&Ws [kk*64 + tx*4];
            float av[4] = {a.x, a.y, a.z, a.w};
            float bv_[4] = {b.x, b.y, b.z, b.w};
#pragma unroll
            for (int r = 0; r < 4; r++)
#pragma unroll
                for (int c = 0; c < 4; c++) acc[r][c] += av[r] * bv_[c];
        }
    }

#pragma unroll
    for (int r = 0; r < 4; r++) {
        int row = r0 + ty*4 + r;            // over B*SEQ
        int bI  = row >> 9, n = row & 511;
        float mm = mask[row] * extra;
#pragma unroll
        for (int c = 0; c < 4; c++) {
            int col = c0 + tx*4 + c;        // over H*D
            int h = col >> 7, d = col & 127;
            out[(((size_t)bI*NH + h)*SEQ + n)*DH + d] = (acc[r][c] + bias[col]) * mm;
        }
    }
}

// ---------------------------------------------------------------------------
// Flash attention: per (b,h), 64 query rows per CTA, stream 8 key tiles of 64.
// grid: (SEQ/64, BB*NH)   block: 256 (16x16), dynamic smem ~112KB
// ---------------------------------------------------------------------------
__global__ __launch_bounds__(256) void attn_kernel(
    const float* __restrict__ dist, const float* __restrict__ mask)
{
    extern __shared__ float sm[];
    float* QsT = sm;                 // [d][i]   128*64
    float* KsT = QsT + 128*64;       // [d][j]   128*64
    float* Vs  = KsT + 128*64;       // [j][d]    64*128
    float* Ps  = Vs  + 64*128;       // [i][j]    64*64
    float* Ms  = Ps  + 64*64;        // [j]       64

    const int tid = threadIdx.x;
    const int tx = tid & 15, ty = tid >> 4;
    const int bh = blockIdx.y;
    const int b  = bh >> 3;
    const int h  = bh & 7;
    const int q0 = blockIdx.x * 64;

    const float* qbase = g_q + (size_t)bh * SEQ * DH;
    const float* kbase = g_k + (size_t)bh * SEQ * DH;
    const float* vbase = g_v + (size_t)bh * SEQ * DH;

    for (int i = tid; i < 64*128; i += 256) {
        int r = i >> 7, d = i & 127;
        QsT[d*64 + r] = qbase[(size_t)(q0 + r) * DH + d];
    }

    float m_i[4], l_i[4], O[4][8];
#pragma unroll
    for (int r = 0; r < 4; r++) {
        m_i[r] = -1e30f; l_i[r] = 0.0f;
#pragma unroll
        for (int c = 0; c < 8; c++) O[r][c] = 0.0f;
    }

    for (int kt = 0; kt < 8; kt++) {
        __syncthreads();  // previous iter's Ps/Vs/KsT fully consumed
        const int k0 = kt * 64;
        for (int i = tid; i < 64*128; i += 256) {
            int r = i >> 7, d = i & 127;
            KsT[d*64 + r] = kbase[(size_t)(k0 + r) * DH + d];
            Vs[i] = vbase[(size_t)k0 * DH + i];
        }
        if (tid < 64) Ms[tid] = mask[b*SEQ + k0 + tid];
        __syncthreads();

        // S = Q @ K^T  (4x4 per thread)
        float acc[4][4];
#pragma unroll
        for (int r = 0; r < 4; r++)
#pragma unroll
            for (int c = 0; c < 4; c++) acc[r][c] = 0.0f;
#pragma unroll 4
        for (int d = 0; d < 128; d++) {
            float4 a = *(const float4*)&QsT[d*64 + ty*4];
            float4 k4 = *(const float4*)&KsT[d*64 + tx*4];
            float av[4] = {a.x, a.y, a.z, a.w};
            float kv[4] = {k4.x, k4.y, k4.z, k4.w};
#pragma unroll
            for (int r = 0; r < 4; r++)
#pragma unroll
                for (int c = 0; c < 4; c++) acc[r][c] += av[r] * kv[c];
        }

        float km[4];
#pragma unroll
        for (int c = 0; c < 4; c++) km[c] = Ms[tx*4 + c];

#pragma unroll
        for (int r = 0; r < 4; r++) {
            const int n = q0 + ty*4 + r;
            float4 dv = *(const float4*)&dist[((size_t)b*SEQ + n)*SEQ + k0 + tx*4];
            float dvals[4] = {dv.x, dv.y, dv.z, dv.w};
            float tmax = -1e30f;
#pragma unroll
            for (int c = 0; c < 4; c++) {
                float s = acc[r][c] + dvals[c];
                s = (km[c] != 0.0f) ? s : -1e30f;
                acc[r][c] = s;
                tmax = fmaxf(tmax, s);
            }
#pragma unroll
            for (int o = 8; o >= 1; o >>= 1)
                tmax = fmaxf(tmax, __shfl_xor_sync(0xffffffffu, tmax, o));

            float mnew = fmaxf(m_i[r], tmax);
            float corr = __expf(m_i[r] - mnew);
            float p[4];
            float rsum = 0.0f;
#pragma unroll
            for (int c = 0; c < 4; c++) {
                float pv = (km[c] != 0.0f) ? __expf(acc[r][c] - mnew) : 0.0f;
                p[c] = pv;
                rsum += pv;
            }
#pragma unroll
            for (int o = 8; o >= 1; o >>= 1)
                rsum += __shfl_xor_sync(0xffffffffu, rsum, o);

            l_i[r] = l_i[r] * corr + rsum;
            m_i[r] = mnew;
#pragma unroll
            for (int c = 0; c < 8; c++) O[r][c] *= corr;
            *(float4*)&Ps[(ty*4 + r)*64 + tx*4] = make_float4(p[0], p[1], p[2], p[3]);
        }
        __syncthreads();

        // O += P @ V
#pragma unroll 2
        for (int kk = 0; kk < 64; kk++) {
            float pr[4];
#pragma unroll
            for (int r = 0; r < 4; r++) pr[r] = Ps[(ty*4 + r)*64 + kk];
            float4 v0 = *(const float4*)&Vs[kk*128 + tx*8];
            float4 v1 = *(const float4*)&Vs[kk*128 + tx*8 + 4];
            float vv[8] = {v0.x, v0.y, v0.z, v0.w, v1.x, v1.y, v1.z, v1.w};
#pragma unroll
            for (int r = 0; r < 4; r++)
#pragma unroll
                for (int c = 0; c < 8; c++) O[r][c] += pr[r] * vv[c];
        }
    }

    // epilogue: normalize and write [B,N,H*D]
#pragma unroll
    for (int r = 0; r < 4; r++) {
        float inv = (l_i[r] > 0.0f) ? 1.0f / l_i[r] : 0.0f;
        int n = q0 + ty*4 + r;
        float* orow = g_y1 + ((size_t)b*SEQ + n)*HD + h*DH + tx*8;
        float4 o0 = make_float4(O[r][0]*inv, O[r][1]*inv, O[r][2]*inv, O[r][3]*inv);
        float4 o1 = make_float4(O[r][4]*inv, O[r][5]*inv, O[r][6]*inv, O[r][7]*inv);
        *(float4*)&orow[0] = o0;
        *(float4*)&orow[4] = o1;
    }
}

// ---------------------------------------------------------------------------
// Output projection: out = (y1 @ Wo + bo) * mask
// grid: (NROWS/64)   block: 256 (16x16, 4x8 micro-tile), K=1024 in chunks of 64
// ---------------------------------------------------------------------------
__global__ __launch_bounds__(256) void oproj_kernel(
    const float* __restrict__ Wo, const float* __restrict__ bo,
    const float* __restrict__ mask, float* __restrict__ out)
{
    __shared__ float AsT[64*64];    // [kk][r]
    __shared__ float Bs [64*128];   // [kk][c]
    const int tid = threadIdx.x;
    const int tx = tid & 15, ty = tid >> 4;
    const int r0 = blockIdx.x * 64;

    float acc[4][8];
#pragma unroll
    for (int r = 0; r < 4; r++)
#pragma unroll
        for (int c = 0; c < 8; c++) acc[r][c] = 0.0f;

    for (int kc = 0; kc < 16; kc++) {
        __syncthreads();
        const int k0 = kc * 64;
        for (int i = tid; i < 4096; i += 256) {
            int r = i >> 6, kk = i & 63;
            AsT[kk*64 + r] = g_y1[(size_t)(r0 + r)*HD + k0 + kk];
        }
        for (int i = tid; i < 64*128; i += 256) {
            int kk = i >> 7, c = i & 127;
            Bs[i] = Wo[(size_t)(k0 + kk)*DH + c];
        }
        __syncthreads();
#pragma unroll 4
        for (int kk = 0; kk < 64; kk++) {
            float4 a  = *(const float4*)&AsT[kk*64 + ty*4];
            float4 b0 = *(const float4*)&Bs [kk*128 + tx*8];
            float4 b1 = *(const float4*)&Bs [kk*128 + tx*8 + 4];
            float av[4] = {a.x, a.y, a.z, a.w};
            float bv_[8] = {b0.x, b0.y, b0.z, b0.w, b1.x, b1.y, b1.z, b1.w};
#pragma unroll
            for (int r = 0; r < 4; r++)
#pragma unroll
                for (int c = 0; c < 8; c++) acc[r][c] += av[r] * bv_[c];
        }
    }

#pragma unroll
    for (int r = 0; r < 4; r++) {
        int row = r0 + ty*4 + r;
        float mm = mask[row];
#pragma unroll
        for (int c = 0; c < 8; c++) {
            int col = tx*8 + c;
            out[(size_t)row*DH + col] = (acc[r][c] + bo[col]) * mm;
        }
    }
}

// ---------------------------------------------------------------------------
extern "C" void kernel_launch(void* const* d_in, const int* in_sizes, int n_in,
                              void* d_out, int out_size)
{
    const float* x    = (const float*)d_in[0];
    const float* dist = (const float*)d_in[1];
    const float* mask = (const float*)d_in[2];
    const float* Wq   = (const float*)d_in[3];
    const float* bq   = (const float*)d_in[4];
    const float* Wk   = (const float*)d_in[5];
    const float* bk   = (const float*)d_in[6];
    const float* Wv   = (const float*)d_in[7];
    const float* bv   = (const float*)d_in[8];
    const float* Wo   = (const float*)d_in[9];
    const float* bo   = (const float*)d_in[10];
    float* out = (float*)d_out;

    const int attn_smem = (128*64*2 + 64*128 + 64*64 + 64) * (int)sizeof(float); // 114944 B
    cudaFuncSetAttribute(attn_kernel, cudaFuncAttributeMaxDynamicSharedMemorySize, attn_smem);

    proj_kernel<<<dim3(HD/64, NROWS/64, 3), 256>>>(x, mask, Wq, bq, Wk, bk, Wv, bv);
    attn_kernel<<<dim3(SEQ/64, BB*NH), 256, attn_smem>>>(dist, mask);
    oproj_kernel<<<dim3(NROWS/64), 256>>>(Wo, bo, mask, out);
}

// round 2
// speedup vs baseline: 3.1517x; 3.1517x over previous
#include <cuda_runtime.h>

#define BB   16
#define SEQ  512
#define NH   8
#define DH   128
#define HD   1024
#define NROWS (BB*SEQ)            // 8192
#define SCALE 0.08838834764831843f

// Scratch (no device allocation allowed)
__device__ float g_q [BB*NH*SEQ*DH];   // [B,H,N,D]  masked*scaled
__device__ float g_k [BB*NH*SEQ*DH];   // [B,H,N,D]  masked
__device__ float g_v [BB*NH*SEQ*DH];   // [B,H,N,D]  masked
__device__ float g_y1[NROWS*HD];       // [B,N,H*D]  attention output

__device__ __forceinline__ unsigned f2tf(float f) {
    unsigned u;
    asm("cvt.rna.tf32.f32 %0, %1;" : "=r"(u) : "f"(f));
    return u;
}

// D (4xf32) += A(16x8 tf32) @ B(8x8 tf32),  A row-major frag, B col-major frag
__device__ __forceinline__ void mma8(float* d, const unsigned* a, const unsigned* b) {
    asm volatile(
        "mma.sync.aligned.m16n8k8.row.col.f32.tf32.tf32.f32 "
        "{%0,%1,%2,%3}, {%4,%5,%6,%7}, {%8,%9}, {%0,%1,%2,%3};"
        : "+f"(d[0]), "+f"(d[1]), "+f"(d[2]), "+f"(d[3])
        : "r"(a[0]), "r"(a[1]), "r"(a[2]), "r"(a[3]), "r"(b[0]), "r"(b[1]));
}

// ---------------------------------------------------------------------------
// QKV projection (tf32 MMA): out = (x @ W + b) * mask (* scale for q) -> [B,H,N,D]
// grid: (HD/128, NROWS/128, 3)  block: 256 (8 warps: 4 in M x 2 in N)
// CTA tile 128x128, K staged 32
// ---------------------------------------------------------------------------
__global__ __launch_bounds__(256) void proj_kernel(
    const float* __restrict__ x,  const float* __restrict__ mask,
    const float* __restrict__ Wq, const float* __restrict__ bq,
    const float* __restrict__ Wk, const float* __restrict__ bk,
    const float* __restrict__ Wv, const float* __restrict__ bv)
{
    __shared__ unsigned As[128*36];   // [m][k] tf32, stride 36
    __shared__ unsigned Bs[128*36];   // [n][k] tf32 (W transposed), stride 36

    const int tid = threadIdx.x;
    const int wid = tid >> 5, lane = tid & 31;
    const int g = lane >> 2, c = lane & 3;
    const int wm = wid & 3, wn = wid >> 2;       // warp tile: 32 x 64
    const int c0 = blockIdx.x * 128;
    const int r0 = blockIdx.y * 128;
    const int sel = blockIdx.z;
    const float* W    = (sel == 0) ? Wq : (sel == 1) ? Wk : Wv;
    const float* bias = (sel == 0) ? bq : (sel == 1) ? bk : bv;
    float*       out  = (sel == 0) ? g_q : (sel == 1) ? g_k : g_v;
    const float extra = (sel == 0) ? SCALE : 1.0f;

    float acc[2][8][4];
#pragma unroll
    for (int mf = 0; mf < 2; mf++)
#pragma unroll
        for (int nf = 0; nf < 8; nf++)
#pragma unroll
            for (int i = 0; i < 4; i++) acc[mf][nf][i] = 0.0f;

    for (int ks = 0; ks < 4; ks++) {
        const int k0 = ks * 32;
        __syncthreads();
        // A tile: x[r0..+128][k0..+32]
        for (int i = tid; i < 1024; i += 256) {
            int row = i >> 3, kq = (i & 7) * 4;
            float4 v = *(const float4*)&x[(size_t)(r0 + row) * DH + k0 + kq];
            unsigned* dst = &As[row * 36 + kq];
            dst[0] = f2tf(v.x); dst[1] = f2tf(v.y); dst[2] = f2tf(v.z); dst[3] = f2tf(v.w);
        }
        // B tile (transposed): W[k0..+32][c0..+128] -> Bs[n][k]
        for (int i = tid; i < 1024; i += 256) {
            int kk = i >> 5, nq = (i & 31) * 4;
            float4 v = *(const float4*)&W[(size_t)(k0 + kk) * HD + c0 + nq];
            Bs[(nq + 0) * 36 + kk] = f2tf(v.x);
            Bs[(nq + 1) * 36 + kk] = f2tf(v.y);
            Bs[(nq + 2) * 36 + kk] = f2tf(v.z);
            Bs[(nq + 3) * 36 + kk] = f2tf(v.w);
        }
        __syncthreads();

#pragma unroll
        for (int kk = 0; kk < 4; kk++) {
            const int kb = kk * 8;
            unsigned a[2][4];
#pragma unroll
            for (int mf = 0; mf < 2; mf++) {
                int row = wm * 32 + mf * 16;
                a[mf][0] = As[(row + g) * 36 + kb + c];
                a[mf][1] = As[(row + g + 8) * 36 + kb + c];
                a[mf][2] = As[(row + g) * 36 + kb + c + 4];
                a[mf][3] = As[(row + g + 8) * 36 + kb + c + 4];
            }
#pragma unroll
            for (int nf = 0; nf < 8; nf++) {
                int col = wn * 64 + nf * 8;
                unsigned b[2];
                b[0] = Bs[(col + g) * 36 + kb + c];
                b[1] = Bs[(col + g) * 36 + kb + c + 4];
#pragma unroll
                for (int mf = 0; mf < 2; mf++) mma8(acc[mf][nf], a[mf], b);
            }
        }
    }

    // epilogue: (acc + bias) * mask(*scale), scatter to [B,H,N,D]
#pragma unroll
    for (int mf = 0; mf < 2; mf++) {
#pragma unroll
        for (int rr = 0; rr < 2; rr++) {
            int row = r0 + wm * 32 + mf * 16 + g + rr * 8;   // over B*SEQ
            int bI = row >> 9, n = row & 511;
            float mm = mask[row] * extra;
#pragma unroll
            for (int nf = 0; nf < 8; nf++) {
                int col = c0 + wn * 64 + nf * 8 + 2 * c;     // over H*D (even)
                int h = col >> 7, d = col & 127;
                float v0 = (acc[mf][nf][rr * 2 + 0] + bias[col]) * mm;
                float v1 = (acc[mf][nf][rr * 2 + 1] + bias[col + 1]) * mm;
                *(float2*)&out[(((size_t)bI * NH + h) * SEQ + n) * DH + d] =
                    make_float2(v0, v1);
            }
        }
    }
}

// ---------------------------------------------------------------------------
// Flash attention (tf32 MMA): per (b,h), 128 q-rows per CTA, 8 key tiles of 64
// grid: (SEQ/128, BB*NH)  block: 256 (8 warps, each owns 16 q-rows)
// ---------------------------------------------------------------------------
__global__ __launch_bounds__(256, 1) void attn_kernel(
    const float* __restrict__ dist, const float* __restrict__ mask)
{
    extern __shared__ unsigned smu[];
    unsigned* Qs = smu;                 // [128][132] tf32
    unsigned* Ks = Qs + 128 * 132;      // [64][132]  tf32
    float*    Vs = (float*)(Ks + 64 * 132); // [64][136] fp32
    unsigned* Ps = (unsigned*)(Vs + 64 * 136); // [128][68] tf32
    float*    Ms = (float*)(Ps + 128 * 68);    // [64]

    const int tid = threadIdx.x;
    const int wid = tid >> 5, lane = tid & 31;
    const int g = lane >> 2, c = lane & 3;
    const int bh = blockIdx.y;
    const int b = bh >> 3, h = bh & 7;
    const int q0 = blockIdx.x * 128;
    const int m0 = wid * 16;            // warp's q-row base (local)

    const float* qbase = g_q + (size_t)bh * SEQ * DH;
    const float* kbase = g_k + (size_t)bh * SEQ * DH;
    const float* vbase = g_v + (size_t)bh * SEQ * DH;

    // load Q tile -> tf32 smem
    for (int i = tid; i < 4096; i += 256) {
        int row = i >> 5, dq = (i & 31) * 4;
        float4 v = *(const float4*)&qbase[(size_t)(q0 + row) * DH + dq];
        unsigned* dst = &Qs[row * 132 + dq];
        dst[0] = f2tf(v.x); dst[1] = f2tf(v.y); dst[2] = f2tf(v.z); dst[3] = f2tf(v.w);
    }

    float O[16][4];
#pragma unroll
    for (int nf = 0; nf < 16; nf++)
#pragma unroll
        for (int i = 0; i < 4; i++) O[nf][i] = 0.0f;
    float m_i[2] = {-1e30f, -1e30f};
    float l_i[2] = {0.0f, 0.0f};

    for (int kt = 0; kt < 8; kt++) {
        const int k0 = kt * 64;
        __syncthreads();
        for (int i = tid; i < 2048; i += 256) {
            int row = i >> 5, dq = (i & 31) * 4;
            float4 kv = *(const float4*)&kbase[(size_t)(k0 + row) * DH + dq];
            unsigned* dk = &Ks[row * 132 + dq];
            dk[0] = f2tf(kv.x); dk[1] = f2tf(kv.y); dk[2] = f2tf(kv.z); dk[3] = f2tf(kv.w);
            float4 vv = *(const float4*)&vbase[(size_t)(k0 + row) * DH + dq];
            *(float4*)&Vs[row * 136 + dq] = vv;
        }
        if (tid < 64) Ms[tid] = mask[b * SEQ + k0 + tid];
        __syncthreads();

        // S = Q @ K^T : warp tile 16 x 64
        float s[8][4];
#pragma unroll
        for (int nf = 0; nf < 8; nf++)
#pragma unroll
            for (int i = 0; i < 4; i++) s[nf][i] = 0.0f;
#pragma unroll
        for (int kk = 0; kk < 16; kk++) {
            const int kb = kk * 8;
            unsigned a[4];
            a[0] = Qs[(m0 + g) * 132 + kb + c];
            a[1] = Qs[(m0 + g + 8) * 132 + kb + c];
            a[2] = Qs[(m0 + g) * 132 + kb + c + 4];
            a[3] = Qs[(m0 + g + 8) * 132 + kb + c + 4];
#pragma unroll
            for (int nf = 0; nf < 8; nf++) {
                unsigned bfr[2];
                bfr[0] = Ks[(nf * 8 + g) * 132 + kb + c];
                bfr[1] = Ks[(nf * 8 + g) * 132 + kb + c + 4];
                mma8(s[nf], a, bfr);
            }
        }

        // add dist, mask, online softmax (rows: g and g+8)
        float corr[2];
#pragma unroll
        for (int rr = 0; rr < 2; rr++) {
            const int n = q0 + m0 + g + rr * 8;
            const float* drow = &dist[((size_t)b * SEQ + n) * SEQ + k0];
            float tmax = -1e30f;
            float pv[8][2];
#pragma unroll
            for (int nf = 0; nf < 8; nf++) {
                int col = nf * 8 + 2 * c;
                float2 dv = *(const float2*)&drow[col];
                float km0 = Ms[col], km1 = Ms[col + 1];
                float s0 = s[nf][rr * 2 + 0] + dv.x;
                float s1 = s[nf][rr * 2 + 1] + dv.y;
                s0 = (km0 != 0.0f) ? s0 : -1e30f;
                s1 = (km1 != 0.0f) ? s1 : -1e30f;
                pv[nf][0] = s0; pv[nf][1] = s1;
                tmax = fmaxf(tmax, fmaxf(s0, s1));
            }
            tmax = fmaxf(tmax, __shfl_xor_sync(0xffffffffu, tmax, 1));
            tmax = fmaxf(tmax, __shfl_xor_sync(0xffffffffu, tmax, 2));
            float mnew = fmaxf(m_i[rr], tmax);
            corr[rr] = __expf(m_i[rr] - mnew);
            m_i[rr] = mnew;
            float rsum = 0.0f;
#pragma unroll
            for (int nf = 0; nf < 8; nf++) {
                float p0 = (pv[nf][0] > -1e29f) ? __expf(pv[nf][0] - mnew) : 0.0f;
                float p1 = (pv[nf][1] > -1e29f) ? __expf(pv[nf][1] - mnew) : 0.0f;
                rsum += p0 + p1;
                int col = nf * 8 + 2 * c;
                Ps[(m0 + g + rr * 8) * 68 + col] = f2tf(p0);
                Ps[(m0 + g + rr * 8) * 68 + col + 1] = f2tf(p1);
            }
            rsum += __shfl_xor_sync(0xffffffffu, rsum, 1);
            rsum += __shfl_xor_sync(0xffffffffu, rsum, 2);
            l_i[rr] = l_i[rr] * corr[rr] + rsum;
        }
        // rescale O
#pragma unroll
        for (int nf = 0; nf < 16; nf++) {
            O[nf][0] *= corr[0]; O[nf][1] *= corr[0];
            O[nf][2] *= corr[1]; O[nf][3] *= corr[1];
        }
        __syncwarp();

        // O += P @ V : warp tile 16 x 128, k = 64
#pragma unroll
        for (int kk = 0; kk < 8; kk++) {
            const int kb = kk * 8;
            unsigned a[4];
            a[0] = Ps[(m0 + g) * 68 + kb + c];
            a[1] = Ps[(m0 + g + 8) * 68 + kb + c];
            a[2] = Ps[(m0 + g) * 68 + kb + c + 4];
            a[3] = Ps[(m0 + g + 8) * 68 + kb + c + 4];
#pragma unroll
            for (int nf = 0; nf < 16; nf++) {
                unsigned bfr[2];
                bfr[0] = f2tf(Vs[(kb + c) * 136 + nf * 8 + g]);
                bfr[1] = f2tf(Vs[(kb + c + 4) * 136 + nf * 8 + g]);
                mma8(O[nf], a, bfr);
            }
        }
    }

    // epilogue: normalize, write [B,N,H*D]
#pragma unroll
    for (int rr = 0; rr < 2; rr++) {
        float inv = (l_i[rr] > 0.0f) ? 1.0f / l_i[rr] : 0.0f;
        int n = q0 + m0 + g + rr * 8;
        float* orow = g_y1 + ((size_t)b * SEQ + n) * HD + h * DH;
#pragma unroll
        for (int nf = 0; nf < 16; nf++) {
            int col = nf * 8 + 2 * c;
            *(float2*)&orow[col] = make_float2(O[nf][rr * 2 + 0] * inv,
                                               O[nf][rr * 2 + 1] * inv);
        }
    }
}

// ---------------------------------------------------------------------------
// Output projection (tf32 MMA): out = (y1 @ Wo + bo) * mask
// grid: NROWS/64   block: 256 (8 warps: 4 in M x 2 in N), tile 64x128, K=1024
// ---------------------------------------------------------------------------
__global__ __launch_bounds__(256) void oproj_kernel(
    const float* __restrict__ Wo, const float* __restrict__ bo,
    const float* __restrict__ mask, float* __restrict__ out)
{
    __shared__ unsigned As[64*36];    // [m][k]
    __shared__ unsigned Bs[128*36];   // [n][k]

    const int tid = threadIdx.x;
    const int wid = tid >> 5, lane = tid & 31;
    const int g = lane >> 2, c = lane & 3;
    const int wm = wid & 3, wn = wid >> 2;      // warp tile 16 x 64
    const int r0 = blockIdx.x * 64;

    float acc[8][4];
#pragma unroll
    for (int nf = 0; nf < 8; nf++)
#pragma unroll
        for (int i = 0; i < 4; i++) acc[nf][i] = 0.0f;

    for (int ks = 0; ks < 32; ks++) {
        const int k0 = ks * 32;
        __syncthreads();
        for (int i = tid; i < 512; i += 256) {
            int row = i >> 3, kq = (i & 7) * 4;
            float4 v = *(const float4*)&g_y1[(size_t)(r0 + row) * HD + k0 + kq];
            unsigned* dst = &As[row * 36 + kq];
            dst[0] = f2tf(v.x); dst[1] = f2tf(v.y); dst[2] = f2tf(v.z); dst[3] = f2tf(v.w);
        }
        for (int i = tid; i < 1024; i += 256) {
            int kk = i >> 5, nq = (i & 31) * 4;
            float4 v = *(const float4*)&Wo[(size_t)(k0 + kk) * DH + nq];
            Bs[(nq + 0) * 36 + kk] = f2tf(v.x);
            Bs[(nq + 1) * 36 + kk] = f2tf(v.y);
            Bs[(nq + 2) * 36 + kk] = f2tf(v.z);
            Bs[(nq + 3) * 36 + kk] = f2tf(v.w);
        }
        __syncthreads();

#pragma unroll
        for (int kk = 0; kk < 4; kk++) {
            const int kb = kk * 8;
            unsigned a[4];
            int row = wm * 16;
            a[0] = As[(row + g) * 36 + kb + c];
            a[1] = As[(row + g + 8) * 36 + kb + c];
            a[2] = As[(row + g) * 36 + kb + c + 4];
            a[3] = As[(row + g + 8) * 36 + kb + c + 4];
#pragma unroll
            for (int nf = 0; nf < 8; nf++) {
                int col = wn * 64 + nf * 8;
                unsigned bfr[2];
                bfr[0] = Bs[(col + g) * 36 + kb + c];
                bfr[1] = Bs[(col + g) * 36 + kb + c + 4];
                mma8(acc[nf], a, bfr);
            }
        }
    }

#pragma unroll
    for (int rr = 0; rr < 2; rr++) {
        int row = r0 + wm * 16 + g + rr * 8;
        float mm = mask[row];
#pragma unroll
        for (int nf = 0; nf < 8; nf++) {
            int col = wn * 64 + nf * 8 + 2 * c;
            float v0 = (acc[nf][rr * 2 + 0] + bo[col]) * mm;
            float v1 = (acc[nf][rr * 2 + 1] + bo[col + 1]) * mm;
            *(float2*)&out[(size_t)row * DH + col] = make_float2(v0, v1);
        }
    }
}

// ---------------------------------------------------------------------------
extern "C" void kernel_launch(void* const* d_in, const int* in_sizes, int n_in,
                              void* d_out, int out_size)
{
    const float* x    = (const float*)d_in[0];
    const float* dist = (const float*)d_in[1];
    const float* mask = (const float*)d_in[2];
    const float* Wq   = (const float*)d_in[3];
    const float* bq   = (const float*)d_in[4];
    const float* Wk   = (const float*)d_in[5];
    const float* bk   = (const float*)d_in[6];
    const float* Wv   = (const float*)d_in[7];
    const float* bv   = (const float*)d_in[8];
    const float* Wo   = (const float*)d_in[9];
    const float* bo   = (const float*)d_in[10];
    float* out = (float*)d_out;

    // Qs 128*132 + Ks 64*132 + Vs 64*136 + Ps 128*68 + Ms 64  (x4 bytes)
    const int attn_smem = (128*132 + 64*132 + 64*136 + 128*68 + 64) * 4; // 171264
    static int configured = 0;
    if (!configured) {
        cudaFuncSetAttribute(attn_kernel, cudaFuncAttributeMaxDynamicSharedMemorySize, attn_smem);
        configured = 1;
    }

    proj_kernel<<<dim3(HD/128, NROWS/128, 3), 256>>>(x, mask, Wq, bq, Wk, bk, Wv, bv);
    attn_kernel<<<dim3(SEQ/128, BB*NH), 256, attn_smem>>>(dist, mask);
    oproj_kernel<<<dim3(NROWS/64), 256>>>(Wo, bo, mask, out);
}